// round 4
// baseline (speedup 1.0000x reference)
#include <cuda_runtime.h>
#include <cstdint>

#define Hdim 256
#define Sdim 512
#define Bdim 4
#define NROWS (Bdim * Sdim)   // 2048

// scratch: projected h (with b_h folded), h', softmax denominators
__device__ float g_ht[NROWS * Hdim];
__device__ float g_htp[NROWS * Hdim];
__device__ float g_den[NROWS];

__device__ __forceinline__ float fast_tanh(float x) {
    float y;
    asm("tanh.approx.f32 %0, %1;" : "=f"(y) : "f"(x));
    return y;
}

// ---------------------------------------------------------------------------
// Kernel A: ht = h @ W_t + b_h ; htp = h @ W_t'
// ---------------------------------------------------------------------------
#define KA_ROWS 16

__global__ __launch_bounds__(256, 2)
void proj_kernel(const float* __restrict__ h,
                 const float* __restrict__ Wt,
                 const float* __restrict__ Wtp,
                 const float* __restrict__ bh)
{
    __shared__ __align__(16) float sHT[Hdim][20];  // transposed [h][row], padded
    const int row0 = blockIdx.x * KA_ROWS;
    const int tid = threadIdx.x;

    const float4* h4 = reinterpret_cast<const float4*>(h + (size_t)row0 * Hdim);
#pragma unroll
    for (int i = 0; i < 4; i++) {
        int idx = tid + i * 256;       // f4 index over 16x64
        int r = idx >> 6;
        int c4 = idx & 63;
        float4 v = h4[idx];
        int c = c4 * 4;
        sHT[c + 0][r] = v.x;
        sHT[c + 1][r] = v.y;
        sHT[c + 2][r] = v.z;
        sHT[c + 3][r] = v.w;
    }
    __syncthreads();

    const int k = tid;
    float accT[KA_ROWS], accP[KA_ROWS];
#pragma unroll
    for (int r = 0; r < KA_ROWS; r++) { accT[r] = 0.f; accP[r] = 0.f; }

#pragma unroll 4
    for (int hh = 0; hh < Hdim; hh++) {
        float wt = __ldg(&Wt[hh * Hdim + k]);
        float wp = __ldg(&Wtp[hh * Hdim + k]);
        const float4* hv4 = reinterpret_cast<const float4*>(&sHT[hh][0]);
        float4 v0 = hv4[0], v1 = hv4[1], v2 = hv4[2], v3 = hv4[3];
        float hv[16] = { v0.x, v0.y, v0.z, v0.w,
                         v1.x, v1.y, v1.z, v1.w,
                         v2.x, v2.y, v2.z, v2.w,
                         v3.x, v3.y, v3.z, v3.w };
#pragma unroll
        for (int r = 0; r < KA_ROWS; r++) {
            accT[r] = fmaf(hv[r], wt, accT[r]);
            accP[r] = fmaf(hv[r], wp, accP[r]);
        }
    }

    const float bhk = bh[k];
#pragma unroll
    for (int r = 0; r < KA_ROWS; r++) {
        g_ht [(size_t)(row0 + r) * Hdim + k] = accT[r] + bhk;
        g_htp[(size_t)(row0 + r) * Hdim + k] = accP[r];
    }
}

// ---------------------------------------------------------------------------
// Kernel B (fused): per tile of 8 t' rows: scores -> ev -> unnormalized
// num/den accumulation. 128 threads = 4 warps; warp w owns t = rowbase + w.
// Lane l: r = l>>3 owns t' rows {r, r+4}; kq = l&7 owns f4 cols {kq+8g}.
// 3-slot cp.async ring, ONE __syncthreads per tile.
// ---------------------------------------------------------------------------
#define TT 4
#define TP 8
#define NTILE (Sdim / TP)   // 64
#define NSTAGE 3

__global__ __launch_bounds__(128, 4)
void attn_fused(const float* __restrict__ Wa,
                const float* __restrict__ ba_p,
                float* __restrict__ out,
                float* __restrict__ attn)
{
    extern __shared__ __align__(16) char smem_raw[];
    float* sP  = reinterpret_cast<float*>(smem_raw);       // [3][8][256]
    float* sH  = sP + NSTAGE * TP * Hdim;                  // [3][8][256]
    float* sHt = sH + NSTAGE * TP * Hdim;                  // [4][256]
    float* sWa = sHt + TT * Hdim;                          // [256]
    float* sEv = sWa + Hdim;                               // [4][8]

    const int tid = threadIdx.x;
    const int w = tid >> 5;
    const int l = tid & 31;
    const int rowbase = blockIdx.x * TT;       // global (b*S + t)
    const int b = rowbase >> 9;                // /512

    const float* htp_b = g_htp + (size_t)b * Sdim * Hdim;
    const float* h_b   = g_ht  - 0;            // placeholder; real h passed below
    (void)h_b;

    const float* h_src;   // original h rows for this batch (set in launch arg trick)
    // we pass h via attn pointer arithmetic? No — add as kernel arg instead.
    h_src = nullptr;      // (unused; see real parameter version below)
    (void)h_src;

    // NOTE: real h passed as last param; see signature fix-up below.
    // --- this block intentionally replaced by the real implementation ---
    // (kept minimal; see attn_fused_impl)
    (void)Wa; (void)ba_p; (void)out; (void)attn; (void)sP; (void)sEv;
}

// Real fused kernel (with h parameter).
__global__ __launch_bounds__(128, 4)
void attn_fused2(const float* __restrict__ h,
                 const float* __restrict__ Wa,
                 const float* __restrict__ ba_p,
                 float* __restrict__ out,
                 float* __restrict__ attn)
{
    extern __shared__ __align__(16) char smem_raw[];
    float* sP  = reinterpret_cast<float*>(smem_raw);       // [3][8][256] 24576 B
    float* sH  = sP + NSTAGE * TP * Hdim;                  // [3][8][256] 24576 B
    float* sHt = sH + NSTAGE * TP * Hdim;                  // [4][256]     4096 B
    float* sWa = sHt + TT * Hdim;                          // [256]        1024 B
    float* sEv = sWa + Hdim;                               // [4][8]        128 B

    const int tid = threadIdx.x;
    const int w = tid >> 5;
    const int l = tid & 31;
    const int rowbase = blockIdx.x * TT;
    const int b = rowbase >> 9;

    const float* htp_b = g_htp + (size_t)b * Sdim * Hdim;
    const float* h_b   = h     + (size_t)b * Sdim * Hdim;

    auto stageTile = [&](int slot, int tile) {
        const float4* srcP = reinterpret_cast<const float4*>(htp_b + (size_t)tile * TP * Hdim);
        const float4* srcH = reinterpret_cast<const float4*>(h_b   + (size_t)tile * TP * Hdim);
        float* dP = sP + slot * TP * Hdim;
        float* dH = sH + slot * TP * Hdim;
#pragma unroll
        for (int i = 0; i < 4; i++) {
            int idx = tid + i * 128;   // f4 index, 0..511
            uint32_t aP = (uint32_t)__cvta_generic_to_shared(dP + idx * 4);
            uint32_t aH = (uint32_t)__cvta_generic_to_shared(dH + idx * 4);
            asm volatile("cp.async.cg.shared.global [%0], [%1], 16;\n" :: "r"(aP), "l"(srcP + idx));
            asm volatile("cp.async.cg.shared.global [%0], [%1], 16;\n" :: "r"(aH), "l"(srcH + idx));
        }
        asm volatile("cp.async.commit_group;\n");
    };

    // prologue: stage tiles 0 and 1
    stageTile(0, 0);
    stageTile(1, 1);

    // stage per-warp ht row + Wa (plain; published by first barrier)
    {
        const float4* r4 = reinterpret_cast<const float4*>(g_ht + (size_t)(rowbase + w) * Hdim);
        reinterpret_cast<float4*>(sHt + w * Hdim)[l]      = r4[l];
        reinterpret_cast<float4*>(sHt + w * Hdim)[l + 32] = r4[l + 32];
        if (tid < 64)
            reinterpret_cast<float4*>(sWa)[tid] = reinterpret_cast<const float4*>(Wa)[tid];
    }
    const float ba = ba_p[0];

    const int r  = l >> 3;   // owns rows {r, r+4} of each 8-row tile
    const int kq = l & 7;    // f4 slices {kq + 8g}

    float4 o0 = make_float4(0.f, 0.f, 0.f, 0.f);
    float4 o1 = make_float4(0.f, 0.f, 0.f, 0.f);
    float den = 0.f;

    float* attn_row = attn + (size_t)(rowbase + w) * Sdim;

    for (int tile = 0; tile < NTILE; tile++) {
        const int slot = tile % NSTAGE;
        if (tile < NTILE - 1)
            asm volatile("cp.async.wait_group 1;\n");
        else
            asm volatile("cp.async.wait_group 0;\n");
        __syncthreads();     // tile data visible; everyone finished previous tile's reads

        if (tile + 2 < NTILE)
            stageTile((tile + 2) % NSTAGE, tile + 2);   // slot freed last iteration

        // ---- scores for rows r, r+4 ----
        const float* P = sP + slot * TP * Hdim;
        float a0 = 0.f, a1 = 0.f;
#pragma unroll
        for (int g = 0; g < 8; g++) {
            const int f4i = kq + 8 * g;
            float4 q  = *reinterpret_cast<const float4*>(sHt + w * Hdim + f4i * 4);
            float4 av = *reinterpret_cast<const float4*>(sWa + f4i * 4);
            float4 p0 = *reinterpret_cast<const float4*>(P + r * Hdim + f4i * 4);
            float4 p1 = *reinterpret_cast<const float4*>(P + (r + 4) * Hdim + f4i * 4);
            a0 = fmaf(av.x, fast_tanh(p0.x + q.x), a0);
            a0 = fmaf(av.y, fast_tanh(p0.y + q.y), a0);
            a0 = fmaf(av.z, fast_tanh(p0.z + q.z), a0);
            a0 = fmaf(av.w, fast_tanh(p0.w + q.w), a0);
            a1 = fmaf(av.x, fast_tanh(p1.x + q.x), a1);
            a1 = fmaf(av.y, fast_tanh(p1.y + q.y), a1);
            a1 = fmaf(av.z, fast_tanh(p1.z + q.z), a1);
            a1 = fmaf(av.w, fast_tanh(p1.w + q.w), a1);
        }
#pragma unroll
        for (int off = 1; off < 8; off <<= 1) {
            a0 += __shfl_xor_sync(0xFFFFFFFFu, a0, off);
            a1 += __shfl_xor_sync(0xFFFFFFFFu, a1, off);
        }

        // ---- ev = exp(sigmoid(s + ba)) (unnormalized softmax weight) ----
        float sg0 = 0.5f * fast_tanh(0.5f * (a0 + ba)) + 0.5f;
        float sg1 = 0.5f * fast_tanh(0.5f * (a1 + ba)) + 0.5f;
        float ev0 = __expf(sg0);
        float ev1 = __expf(sg1);
        den += ev0 + ev1;    // duplicated x8 per group; fixed by off-8/16 reduce at end

        if (kq == 0) {
            sEv[w * 8 + r]     = ev0;
            sEv[w * 8 + r + 4] = ev1;
            attn_row[tile * TP + r]     = ev0;   // unnormalized; norm kernel divides
            attn_row[tile * TP + r + 4] = ev1;
        }
        __syncwarp();

        // ---- accumulate num += ev * h[t'] ; lane owns f4 cols {l, l+32} ----
        const float* Hs = sH + slot * TP * Hdim;
#pragma unroll
        for (int tp = 0; tp < TP; tp++) {
            float e = sEv[w * 8 + tp];
            float4 v0 = *reinterpret_cast<const float4*>(Hs + tp * Hdim + l * 4);
            float4 v1 = *reinterpret_cast<const float4*>(Hs + tp * Hdim + (l + 32) * 4);
            o0.x = fmaf(e, v0.x, o0.x);  o0.y = fmaf(e, v0.y, o0.y);
            o0.z = fmaf(e, v0.z, o0.z);  o0.w = fmaf(e, v0.w, o0.w);
            o1.x = fmaf(e, v1.x, o1.x);  o1.y = fmaf(e, v1.y, o1.y);
            o1.z = fmaf(e, v1.z, o1.z);  o1.w = fmaf(e, v1.w, o1.w);
        }
    }

    // den: groups r=0..3 hold distinct row-sums (each duplicated across 8 lanes)
    den += __shfl_xor_sync(0xFFFFFFFFu, den, 8);
    den += __shfl_xor_sync(0xFFFFFFFFu, den, 16);
    if (l == 0) g_den[rowbase + w] = den;

    float* orow = out + (size_t)(rowbase + w) * Hdim;
    reinterpret_cast<float4*>(orow)[l]      = o0;   // unnormalized
    reinterpret_cast<float4*>(orow)[l + 32] = o1;
}

// ---------------------------------------------------------------------------
// Kernel C: normalize out and attn by 1/den.
// ---------------------------------------------------------------------------
__global__ __launch_bounds__(128, 8)
void norm_kernel(float* __restrict__ out, float* __restrict__ attn)
{
    const int row = blockIdx.x;
    const int tid = threadIdx.x;
    const float inv = __fdividef(1.0f, g_den[row]);

    float4* a4 = reinterpret_cast<float4*>(attn + (size_t)row * Sdim);
    float4 v = a4[tid];
    v.x *= inv; v.y *= inv; v.z *= inv; v.w *= inv;
    a4[tid] = v;

    if (tid < 64) {
        float4* o4 = reinterpret_cast<float4*>(out + (size_t)row * Hdim);
        float4 u = o4[tid];
        u.x *= inv; u.y *= inv; u.z *= inv; u.w *= inv;
        o4[tid] = u;
    }
}

// ---------------------------------------------------------------------------
extern "C" void kernel_launch(void* const* d_in, const int* in_sizes, int n_in,
                              void* d_out, int out_size)
{
    const float* h   = (const float*)d_in[0];
    const float* Wt  = (const float*)d_in[1];
    const float* Wtp = (const float*)d_in[2];
    const float* bh  = (const float*)d_in[3];
    const float* Wa  = (const float*)d_in[4];
    const float* ba  = (const float*)d_in[5];

    float* out  = (float*)d_out;                  // [B,S,H] = 524288
    float* attn = out + (size_t)NROWS * Hdim;     // [B,S,S] = 1048576

    const int smem_bytes = (NSTAGE * TP * Hdim * 2 + TT * Hdim + Hdim + TT * TP) * 4; // 54400
    cudaFuncSetAttribute(attn_fused2, cudaFuncAttributeMaxDynamicSharedMemorySize, smem_bytes);

    proj_kernel<<<NROWS / KA_ROWS, 256>>>(h, Wt, Wtp, bh);
    attn_fused2<<<NROWS / TT, 128, smem_bytes>>>(h, Wa, ba, out, attn);
    norm_kernel<<<NROWS, 128>>>(out, attn);
}

// round 5
// speedup vs baseline: 1.0786x; 1.0786x over previous
#include <cuda_runtime.h>
#include <cstdint>

#define Hdim 256
#define Sdim 512
#define Bdim 4
#define NROWS (Bdim * Sdim)   // 2048

// scratch: projected h (with b_h folded) and h'
__device__ float g_ht[NROWS * Hdim];
__device__ float g_htp[NROWS * Hdim];

__device__ __forceinline__ float fast_tanh(float x) {
    float y;
    asm("tanh.approx.f32 %0, %1;" : "=f"(y) : "f"(x));
    return y;
}

// ---------------------------------------------------------------------------
// Kernel A: ht = h @ W_t + b_h ; htp = h @ W_t'
// 8 rows/block -> 256 blocks (> 148 SMs). Thread k computes column k.
// ---------------------------------------------------------------------------
#define KA_ROWS 8

__global__ __launch_bounds__(256, 4)
void proj_kernel(const float* __restrict__ h,
                 const float* __restrict__ Wt,
                 const float* __restrict__ Wtp,
                 const float* __restrict__ bh)
{
    __shared__ __align__(16) float sHT[Hdim][12];  // transposed [h][row], padded
    const int row0 = blockIdx.x * KA_ROWS;
    const int tid = threadIdx.x;

    const float4* h4 = reinterpret_cast<const float4*>(h + (size_t)row0 * Hdim);
#pragma unroll
    for (int i = 0; i < 2; i++) {
        int idx = tid + i * 256;       // f4 index over 8x64
        int r = idx >> 6;
        int c4 = idx & 63;
        float4 v = h4[idx];
        int c = c4 * 4;
        sHT[c + 0][r] = v.x;
        sHT[c + 1][r] = v.y;
        sHT[c + 2][r] = v.z;
        sHT[c + 3][r] = v.w;
    }
    __syncthreads();

    const int k = tid;
    float accT[KA_ROWS], accP[KA_ROWS];
#pragma unroll
    for (int r = 0; r < KA_ROWS; r++) { accT[r] = 0.f; accP[r] = 0.f; }

#pragma unroll 4
    for (int hh = 0; hh < Hdim; hh++) {
        float wt = __ldg(&Wt[hh * Hdim + k]);
        float wp = __ldg(&Wtp[hh * Hdim + k]);
        const float4* hv4 = reinterpret_cast<const float4*>(&sHT[hh][0]);
        float4 v0 = hv4[0], v1 = hv4[1];
        float hv[8] = { v0.x, v0.y, v0.z, v0.w, v1.x, v1.y, v1.z, v1.w };
#pragma unroll
        for (int r = 0; r < KA_ROWS; r++) {
            accT[r] = fmaf(hv[r], wt, accT[r]);
            accP[r] = fmaf(hv[r], wp, accP[r]);
        }
    }

    const float bhk = bh[k];
#pragma unroll
    for (int r = 0; r < KA_ROWS; r++) {
        g_ht [(size_t)(row0 + r) * Hdim + k] = accT[r] + bhk;
        g_htp[(size_t)(row0 + r) * Hdim + k] = accP[r];
    }
}

// ---------------------------------------------------------------------------
// Kernel B: scores -> ev (unnormalized softmax weights), barrier-free mainloop.
// Block = (b, chunk of 16 t' rows, t-half). htp chunk resident in smem;
// Wa in registers. Warp w streams t = half*256 + 4j + w independently.
// Lane l: r = l>>3 owns chunk rows {r,r+4,r+8,r+12}; kq = l&7 owns f4 slices.
// ---------------------------------------------------------------------------
#define CH 16
#define TSPLIT 2
#define THALF (Sdim / TSPLIT)   // 256

__global__ __launch_bounds__(128, 4)
void score_kernel(const float* __restrict__ Wa,
                  const float* __restrict__ ba_p,
                  float* __restrict__ attn)
{
    __shared__ __align__(16) float sP[CH * Hdim];   // 16 KB

    const int tid = threadIdx.x;
    const int w = tid >> 5;
    const int l = tid & 31;

    const int bi    = blockIdx.x;        // 0..255
    const int half  = bi & 1;
    const int chunk = (bi >> 1) & 31;
    const int b     = bi >> 6;

    // stage htp chunk (once)
    {
        const float4* src = reinterpret_cast<const float4*>(
            g_htp + ((size_t)b * Sdim + chunk * CH) * Hdim);
        float4* dst = reinterpret_cast<float4*>(sP);
#pragma unroll
        for (int i = 0; i < 8; i++)
            dst[tid + i * 128] = src[tid + i * 128];
    }
    __syncthreads();

    const int r  = l >> 3;
    const int kq = l & 7;

    // Wa slices in registers
    float4 a[8];
    const float4* wa4 = reinterpret_cast<const float4*>(Wa);
#pragma unroll
    for (int g = 0; g < 8; g++) a[g] = __ldg(wa4 + kq + 8 * g);
    const float ba = __ldg(ba_p);

    for (int j = 0; j < THALF / 4; j++) {
        const int t = half * THALF + 4 * j + w;
        const float4* q4 = reinterpret_cast<const float4*>(
            g_ht + ((size_t)b * Sdim + t) * Hdim);
        float4 q[8];
#pragma unroll
        for (int g = 0; g < 8; g++) q[g] = __ldg(q4 + kq + 8 * g);

        float acc0 = 0.f, acc1 = 0.f, acc2 = 0.f, acc3 = 0.f;
#pragma unroll
        for (int g = 0; g < 8; g++) {
            const float4 qg = q[g];
            const float4 ag = a[g];
            const int col = (kq + 8 * g) * 4;
            float4 p0 = *reinterpret_cast<const float4*>(&sP[(r     ) * Hdim + col]);
            float4 p1 = *reinterpret_cast<const float4*>(&sP[(r + 4 ) * Hdim + col]);
            float4 p2 = *reinterpret_cast<const float4*>(&sP[(r + 8 ) * Hdim + col]);
            float4 p3 = *reinterpret_cast<const float4*>(&sP[(r + 12) * Hdim + col]);
            acc0 = fmaf(ag.x, fast_tanh(p0.x + qg.x), acc0);
            acc0 = fmaf(ag.y, fast_tanh(p0.y + qg.y), acc0);
            acc0 = fmaf(ag.z, fast_tanh(p0.z + qg.z), acc0);
            acc0 = fmaf(ag.w, fast_tanh(p0.w + qg.w), acc0);
            acc1 = fmaf(ag.x, fast_tanh(p1.x + qg.x), acc1);
            acc1 = fmaf(ag.y, fast_tanh(p1.y + qg.y), acc1);
            acc1 = fmaf(ag.z, fast_tanh(p1.z + qg.z), acc1);
            acc1 = fmaf(ag.w, fast_tanh(p1.w + qg.w), acc1);
            acc2 = fmaf(ag.x, fast_tanh(p2.x + qg.x), acc2);
            acc2 = fmaf(ag.y, fast_tanh(p2.y + qg.y), acc2);
            acc2 = fmaf(ag.z, fast_tanh(p2.z + qg.z), acc2);
            acc2 = fmaf(ag.w, fast_tanh(p2.w + qg.w), acc2);
            acc3 = fmaf(ag.x, fast_tanh(p3.x + qg.x), acc3);
            acc3 = fmaf(ag.y, fast_tanh(p3.y + qg.y), acc3);
            acc3 = fmaf(ag.z, fast_tanh(p3.z + qg.z), acc3);
            acc3 = fmaf(ag.w, fast_tanh(p3.w + qg.w), acc3);
        }
#pragma unroll
        for (int off = 1; off < 8; off <<= 1) {
            acc0 += __shfl_xor_sync(0xFFFFFFFFu, acc0, off);
            acc1 += __shfl_xor_sync(0xFFFFFFFFu, acc1, off);
            acc2 += __shfl_xor_sync(0xFFFFFFFFu, acc2, off);
            acc3 += __shfl_xor_sync(0xFFFFFFFFu, acc3, off);
        }

        // ev = exp(sigmoid(s + ba)) -- unnormalized softmax weight
        float ev0 = __expf(0.5f * fast_tanh(0.5f * (acc0 + ba)) + 0.5f);
        float ev1 = __expf(0.5f * fast_tanh(0.5f * (acc1 + ba)) + 0.5f);
        float ev2 = __expf(0.5f * fast_tanh(0.5f * (acc2 + ba)) + 0.5f);
        float ev3 = __expf(0.5f * fast_tanh(0.5f * (acc3 + ba)) + 0.5f);

        if (kq == 0) {
            float* at = attn + ((size_t)(b * Sdim + t)) * Sdim + chunk * CH;
            at[r     ] = ev0;
            at[r + 4 ] = ev1;
            at[r + 8 ] = ev2;
            at[r + 12] = ev3;
        }
    }
}

// ---------------------------------------------------------------------------
// Kernel C: normalize attn rows (den recomputed from ev row) + output GEMV.
// Block = 8 t rows, 256 threads (8 warps). Warp w owns row rowbase+w for the
// softmax part. GEMV: thread owns f4 col c = l + 32*(w&1) for ALL 8 t rows;
// quarter qd = w>>1 covers 4 of 16 tile rows; partials combined via smem.
// ---------------------------------------------------------------------------
#define TT2 8
#define TPR 16                 // t' rows per tile
#define NT2 (Sdim / TPR)       // 32

__global__ __launch_bounds__(256, 3)
void out_kernel(const float* __restrict__ h,
                float* __restrict__ out,
                float* __restrict__ attn)
{
    __shared__ __align__(16) float sT[2][TPR * Hdim];   // 32768 B
    __shared__ __align__(16) float sS[TT2][Sdim];       // 16384 B

    const int tid = threadIdx.x;
    const int w = tid >> 5;
    const int l = tid & 31;
    const int rowbase = blockIdx.x * TT2;
    const int b = rowbase >> 9;

    const float* h_b = h + (size_t)b * Sdim * Hdim;

    auto stage = [&](int buf, int tile) {
        const float4* src = reinterpret_cast<const float4*>(h_b + (size_t)tile * TPR * Hdim);
        float* dst = sT[buf];
#pragma unroll
        for (int i = 0; i < 4; i++) {
            int idx = tid + i * 256;   // f4 index 0..1023
            uint32_t d = (uint32_t)__cvta_generic_to_shared(dst + idx * 4);
            asm volatile("cp.async.cg.shared.global [%0], [%1], 16;\n"
                         :: "r"(d), "l"(src + idx));
        }
        asm volatile("cp.async.commit_group;\n");
    };

    stage(0, 0);   // prefetch tile 0 under softmax

    // ---- Phase A: den + normalize (warp w -> row rowbase+w) ----
    {
        float4* arow = reinterpret_cast<float4*>(attn + (size_t)(rowbase + w) * Sdim);
        float4 v[4];
        float den = 0.f;
#pragma unroll
        for (int k2 = 0; k2 < 4; k2++) {
            v[k2] = arow[l + 32 * k2];
            den += (v[k2].x + v[k2].y) + (v[k2].z + v[k2].w);
        }
#pragma unroll
        for (int off = 16; off; off >>= 1)
            den += __shfl_xor_sync(0xFFFFFFFFu, den, off);
        const float inv = __fdividef(1.0f, den);
#pragma unroll
        for (int k2 = 0; k2 < 4; k2++) {
            v[k2].x *= inv; v[k2].y *= inv; v[k2].z *= inv; v[k2].w *= inv;
            arow[l + 32 * k2] = v[k2];
            reinterpret_cast<float4*>(sS[w])[l + 32 * k2] = v[k2];
        }
    }

    // ---- Phase B: GEMV over h tiles ----
    const int c  = l + 32 * (w & 1);   // f4 column 0..63
    const int qd = w >> 1;             // row-quarter 0..3
    float4 acc[TT2];
#pragma unroll
    for (int t = 0; t < TT2; t++) acc[t] = make_float4(0.f, 0.f, 0.f, 0.f);

    for (int tile = 0; tile < NT2; tile++) {
        const int buf = tile & 1;
        if (tile + 1 < NT2) {
            stage(buf ^ 1, tile + 1);
            asm volatile("cp.async.wait_group 1;\n");
        } else {
            asm volatile("cp.async.wait_group 0;\n");
        }
        __syncthreads();

#pragma unroll
        for (int tp = 0; tp < 4; tp++) {
            const int trow = 4 * qd + tp;
            float4 hv = *reinterpret_cast<const float4*>(&sT[buf][trow * Hdim + c * 4]);
#pragma unroll
            for (int t = 0; t < TT2; t++) {
                float sv = sS[t][tile * TPR + trow];
                acc[t].x = fmaf(sv, hv.x, acc[t].x);
                acc[t].y = fmaf(sv, hv.y, acc[t].y);
                acc[t].z = fmaf(sv, hv.z, acc[t].z);
                acc[t].w = fmaf(sv, hv.w, acc[t].w);
            }
        }
        __syncthreads();
    }

    // combine quarters: 1..3 write partials, quarter 0 sums + stores
    float4* comb = reinterpret_cast<float4*>(sT);   // 1536 f4 = 24 KB <= 32 KB
    if (qd > 0) {
#pragma unroll
        for (int t = 0; t < TT2; t++)
            comb[(qd - 1) * 512 + t * 64 + c] = acc[t];
    }
    __syncthreads();
    if (qd == 0) {
#pragma unroll
        for (int t = 0; t < TT2; t++) {
            float4 p0 = comb[0 * 512 + t * 64 + c];
            float4 p1 = comb[1 * 512 + t * 64 + c];
            float4 p2 = comb[2 * 512 + t * 64 + c];
            float4 o = acc[t];
            o.x += p0.x + p1.x + p2.x;
            o.y += p0.y + p1.y + p2.y;
            o.z += p0.z + p1.z + p2.z;
            o.w += p0.w + p1.w + p2.w;
            *reinterpret_cast<float4*>(&out[(size_t)(rowbase + t) * Hdim + c * 4]) = o;
        }
    }
}

// ---------------------------------------------------------------------------
extern "C" void kernel_launch(void* const* d_in, const int* in_sizes, int n_in,
                              void* d_out, int out_size)
{
    const float* h   = (const float*)d_in[0];
    const float* Wt  = (const float*)d_in[1];
    const float* Wtp = (const float*)d_in[2];
    const float* bh  = (const float*)d_in[3];
    const float* Wa  = (const float*)d_in[4];
    const float* ba  = (const float*)d_in[5];

    float* out  = (float*)d_out;                  // [B,S,H] = 524288
    float* attn = out + (size_t)NROWS * Hdim;     // [B,S,S] = 1048576

    proj_kernel<<<NROWS / KA_ROWS, 256>>>(h, Wt, Wtp, bh);
    score_kernel<<<Bdim * 32 * TSPLIT, 128>>>(Wa, ba, attn);
    out_kernel<<<NROWS / TT2, 256>>>(h, out, attn);
}

// round 8
// speedup vs baseline: 1.0830x; 1.0041x over previous
#include <cuda_runtime.h>
#include <cstdint>

#define Hdim 256
#define Sdim 512
#define Bdim 4
#define NROWS (Bdim * Sdim)   // 2048

// scratch: projected h (with b_h folded) and h'
__device__ float g_ht[NROWS * Hdim];
__device__ float g_htp[NROWS * Hdim];

__device__ __forceinline__ float fast_tanh(float x) {
    float y;
    asm("tanh.approx.f32 %0, %1;" : "=f"(y) : "f"(x));
    return y;
}

// ---------------------------------------------------------------------------
// Kernel A: ht = h @ W_t + b_h ; htp = h @ W_t'
// 8 rows/block -> 256 blocks. Thread k computes column k.
// k-loop chunked by 8 with register prefetch of the next chunk's W values
// (16 LDG in flight, consumed a full chunk later -> L2 latency hidden).
// ---------------------------------------------------------------------------
#define KA_ROWS 8

__global__ __launch_bounds__(256, 4)
void proj_kernel(const float* __restrict__ h,
                 const float* __restrict__ Wt,
                 const float* __restrict__ Wtp,
                 const float* __restrict__ bh)
{
    __shared__ __align__(16) float sHT[Hdim][12];  // transposed [h][row], padded
    const int row0 = blockIdx.x * KA_ROWS;
    const int tid = threadIdx.x;

    const float4* h4 = reinterpret_cast<const float4*>(h + (size_t)row0 * Hdim);
#pragma unroll
    for (int i = 0; i < 2; i++) {
        int idx = tid + i * 256;       // f4 index over 8x64
        int r = idx >> 6;
        int c4 = idx & 63;
        float4 v = h4[idx];
        int c = c4 * 4;
        sHT[c + 0][r] = v.x;
        sHT[c + 1][r] = v.y;
        sHT[c + 2][r] = v.z;
        sHT[c + 3][r] = v.w;
    }
    __syncthreads();

    const int k = tid;
    float accT[KA_ROWS], accP[KA_ROWS];
#pragma unroll
    for (int r = 0; r < KA_ROWS; r++) { accT[r] = 0.f; accP[r] = 0.f; }

    float wt[8], wp[8];
#pragma unroll
    for (int i = 0; i < 8; i++) {
        wt[i] = __ldg(&Wt [i * Hdim + k]);
        wp[i] = __ldg(&Wtp[i * Hdim + k]);
    }

#pragma unroll 1
    for (int c = 0; c < 32; c++) {
        float nwt[8], nwp[8];
        if (c < 31) {
#pragma unroll
            for (int i = 0; i < 8; i++) {
                const int hh = (c + 1) * 8 + i;
                nwt[i] = __ldg(&Wt [hh * Hdim + k]);
                nwp[i] = __ldg(&Wtp[hh * Hdim + k]);
            }
        }
#pragma unroll
        for (int i = 0; i < 8; i++) {
            const int hh = c * 8 + i;
            const float4* hv4 = reinterpret_cast<const float4*>(&sHT[hh][0]);
            float4 v0 = hv4[0], v1 = hv4[1];
            float hv[8] = { v0.x, v0.y, v0.z, v0.w, v1.x, v1.y, v1.z, v1.w };
            const float wti = wt[i], wpi = wp[i];
#pragma unroll
            for (int r = 0; r < KA_ROWS; r++) {
                accT[r] = fmaf(hv[r], wti, accT[r]);
                accP[r] = fmaf(hv[r], wpi, accP[r]);
            }
        }
#pragma unroll
        for (int i = 0; i < 8; i++) { wt[i] = nwt[i]; wp[i] = nwp[i]; }
    }

    const float bhk = bh[k];
#pragma unroll
    for (int r = 0; r < KA_ROWS; r++) {
        g_ht [(size_t)(row0 + r) * Hdim + k] = accT[r] + bhk;
        g_htp[(size_t)(row0 + r) * Hdim + k] = accP[r];
    }
}

// ---------------------------------------------------------------------------
// Kernel B: scores -> ev (unnormalized softmax weights), barrier-free mainloop.
// Block = (b, chunk of 16 t' rows, t-quarter). htp chunk resident in smem;
// Wa in registers. Warp w streams t = quarter*128 + 4j + w independently.
// Lane l: r = l>>3 owns chunk rows {r,r+4,r+8,r+12}; kq = l&7 owns f4 slices.
// ---------------------------------------------------------------------------
#define CH 16
#define TSPLIT 4
#define TQ (Sdim / TSPLIT)   // 128

__global__ __launch_bounds__(128, 8)
void score_kernel(const float* __restrict__ Wa,
                  const float* __restrict__ ba_p,
                  float* __restrict__ attn)
{
    __shared__ __align__(16) float sP[CH * Hdim];   // 16 KB

    const int tid = threadIdx.x;
    const int w = tid >> 5;
    const int l = tid & 31;

    const int bi    = blockIdx.x;        // 0..511
    const int quart = bi & 3;
    const int chunk = (bi >> 2) & 31;
    const int b     = bi >> 7;

    // stage htp chunk (once)
    {
        const float4* src = reinterpret_cast<const float4*>(
            g_htp + ((size_t)b * Sdim + chunk * CH) * Hdim);
        float4* dst = reinterpret_cast<float4*>(sP);
#pragma unroll
        for (int i = 0; i < 8; i++)
            dst[tid + i * 128] = src[tid + i * 128];
    }
    __syncthreads();

    const int r  = l >> 3;
    const int kq = l & 7;

    // Wa slices in registers
    float4 a[8];
    const float4* wa4 = reinterpret_cast<const float4*>(Wa);
#pragma unroll
    for (int g = 0; g < 8; g++) a[g] = __ldg(wa4 + kq + 8 * g);
    const float ba = __ldg(ba_p);

    for (int j = 0; j < TQ / 4; j++) {
        const int t = quart * TQ + 4 * j + w;
        const float4* q4 = reinterpret_cast<const float4*>(
            g_ht + ((size_t)b * Sdim + t) * Hdim);
        float4 q[8];
#pragma unroll
        for (int g = 0; g < 8; g++) q[g] = __ldg(q4 + kq + 8 * g);

        float acc0 = 0.f, acc1 = 0.f, acc2 = 0.f, acc3 = 0.f;
#pragma unroll
        for (int g = 0; g < 8; g++) {
            const float4 qg = q[g];
            const float4 ag = a[g];
            const int col = (kq + 8 * g) * 4;
            float4 p0 = *reinterpret_cast<const float4*>(&sP[(r     ) * Hdim + col]);
            float4 p1 = *reinterpret_cast<const float4*>(&sP[(r + 4 ) * Hdim + col]);
            float4 p2 = *reinterpret_cast<const float4*>(&sP[(r + 8 ) * Hdim + col]);
            float4 p3 = *reinterpret_cast<const float4*>(&sP[(r + 12) * Hdim + col]);
            acc0 = fmaf(ag.x, fast_tanh(p0.x + qg.x), acc0);
            acc0 = fmaf(ag.y, fast_tanh(p0.y + qg.y), acc0);
            acc0 = fmaf(ag.z, fast_tanh(p0.z + qg.z), acc0);
            acc0 = fmaf(ag.w, fast_tanh(p0.w + qg.w), acc0);
            acc1 = fmaf(ag.x, fast_tanh(p1.x + qg.x), acc1);
            acc1 = fmaf(ag.y, fast_tanh(p1.y + qg.y), acc1);
            acc1 = fmaf(ag.z, fast_tanh(p1.z + qg.z), acc1);
            acc1 = fmaf(ag.w, fast_tanh(p1.w + qg.w), acc1);
            acc2 = fmaf(ag.x, fast_tanh(p2.x + qg.x), acc2);
            acc2 = fmaf(ag.y, fast_tanh(p2.y + qg.y), acc2);
            acc2 = fmaf(ag.z, fast_tanh(p2.z + qg.z), acc2);
            acc2 = fmaf(ag.w, fast_tanh(p2.w + qg.w), acc2);
            acc3 = fmaf(ag.x, fast_tanh(p3.x + qg.x), acc3);
            acc3 = fmaf(ag.y, fast_tanh(p3.y + qg.y), acc3);
            acc3 = fmaf(ag.z, fast_tanh(p3.z + qg.z), acc3);
            acc3 = fmaf(ag.w, fast_tanh(p3.w + qg.w), acc3);
        }
#pragma unroll
        for (int off = 1; off < 8; off <<= 1) {
            acc0 += __shfl_xor_sync(0xFFFFFFFFu, acc0, off);
            acc1 += __shfl_xor_sync(0xFFFFFFFFu, acc1, off);
            acc2 += __shfl_xor_sync(0xFFFFFFFFu, acc2, off);
            acc3 += __shfl_xor_sync(0xFFFFFFFFu, acc3, off);
        }

        // ev = exp(sigmoid(s + ba)) -- unnormalized softmax weight
        float ev0 = __expf(0.5f * fast_tanh(0.5f * (acc0 + ba)) + 0.5f);
        float ev1 = __expf(0.5f * fast_tanh(0.5f * (acc1 + ba)) + 0.5f);
        float ev2 = __expf(0.5f * fast_tanh(0.5f * (acc2 + ba)) + 0.5f);
        float ev3 = __expf(0.5f * fast_tanh(0.5f * (acc3 + ba)) + 0.5f);

        if (kq == 0) {
            float* at = attn + ((size_t)(b * Sdim + t)) * Sdim + chunk * CH;
            at[r     ] = ev0;
            at[r + 4 ] = ev1;
            at[r + 8 ] = ev2;
            at[r + 12] = ev3;
        }
    }
}

// ---------------------------------------------------------------------------
// Kernel C: normalize attn rows (den recomputed from ev row) + output GEMV.
// Block = 8 t rows, 256 threads (8 warps). Warp w owns row rowbase+w for the
// softmax part. GEMV: thread owns f4 col c = l + 32*(w&1) for ALL 8 t rows;
// quarter qd = w>>1 covers 4 of 16 tile rows; partials combined via smem.
// ---------------------------------------------------------------------------
#define TT2 8
#define TPR 16                 // t' rows per tile
#define NT2 (Sdim / TPR)       // 32

__global__ __launch_bounds__(256, 3)
void out_kernel(const float* __restrict__ h,
                float* __restrict__ out,
                float* __restrict__ attn)
{
    __shared__ __align__(16) float sT[2][TPR * Hdim];   // 32768 B
    __shared__ __align__(16) float sS[TT2][Sdim];       // 16384 B

    const int tid = threadIdx.x;
    const int w = tid >> 5;
    const int l = tid & 31;
    const int rowbase = blockIdx.x * TT2;
    const int b = rowbase >> 9;

    const float* h_b = h + (size_t)b * Sdim * Hdim;

    auto stage = [&](int buf, int tile) {
        const float4* src = reinterpret_cast<const float4*>(h_b + (size_t)tile * TPR * Hdim);
        float* dst = sT[buf];
#pragma unroll
        for (int i = 0; i < 4; i++) {
            int idx = tid + i * 256;   // f4 index 0..1023
            uint32_t d = (uint32_t)__cvta_generic_to_shared(dst + idx * 4);
            asm volatile("cp.async.cg.shared.global [%0], [%1], 16;\n"
                         :: "r"(d), "l"(src + idx));
        }
        asm volatile("cp.async.commit_group;\n");
    };

    stage(0, 0);   // prefetch tile 0 under softmax

    // ---- Phase A: den + normalize (warp w -> row rowbase+w) ----
    {
        float4* arow = reinterpret_cast<float4*>(attn + (size_t)(rowbase + w) * Sdim);
        float4 v[4];
        float den = 0.f;
#pragma unroll
        for (int k2 = 0; k2 < 4; k2++) {
            v[k2] = arow[l + 32 * k2];
            den += (v[k2].x + v[k2].y) + (v[k2].z + v[k2].w);
        }
#pragma unroll
        for (int off = 16; off; off >>= 1)
            den += __shfl_xor_sync(0xFFFFFFFFu, den, off);
        const float inv = __fdividef(1.0f, den);
#pragma unroll
        for (int k2 = 0; k2 < 4; k2++) {
            v[k2].x *= inv; v[k2].y *= inv; v[k2].z *= inv; v[k2].w *= inv;
            arow[l + 32 * k2] = v[k2];
            reinterpret_cast<float4*>(sS[w])[l + 32 * k2] = v[k2];
        }
    }

    // ---- Phase B: GEMV over h tiles ----
    const int c  = l + 32 * (w & 1);   // f4 column 0..63
    const int qd = w >> 1;             // row-quarter 0..3
    float4 acc[TT2];
#pragma unroll
    for (int t = 0; t < TT2; t++) acc[t] = make_float4(0.f, 0.f, 0.f, 0.f);

    for (int tile = 0; tile < NT2; tile++) {
        const int buf = tile & 1;
        if (tile + 1 < NT2) {
            stage(buf ^ 1, tile + 1);
            asm volatile("cp.async.wait_group 1;\n");
        } else {
            asm volatile("cp.async.wait_group 0;\n");
        }
        __syncthreads();

#pragma unroll
        for (int tp = 0; tp < 4; tp++) {
            const int trow = 4 * qd + tp;
            float4 hv = *reinterpret_cast<const float4*>(&sT[buf][trow * Hdim + c * 4]);
#pragma unroll
            for (int t = 0; t < TT2; t++) {
                float sv = sS[t][tile * TPR + trow];
                acc[t].x = fmaf(sv, hv.x, acc[t].x);
                acc[t].y = fmaf(sv, hv.y, acc[t].y);
                acc[t].z = fmaf(sv, hv.z, acc[t].z);
                acc[t].w = fmaf(sv, hv.w, acc[t].w);
            }
        }
        __syncthreads();
    }

    // combine quarters: 1..3 write partials, quarter 0 sums + stores
    float4* comb = reinterpret_cast<float4*>(sT);   // 1536 f4 = 24 KB
    if (qd > 0) {
#pragma unroll
        for (int t = 0; t < TT2; t++)
            comb[(qd - 1) * 512 + t * 64 + c] = acc[t];
    }
    __syncthreads();
    if (qd == 0) {
#pragma unroll
        for (int t = 0; t < TT2; t++) {
            float4 p0 = comb[0 * 512 + t * 64 + c];
            float4 p1 = comb[1 * 512 + t * 64 + c];
            float4 p2 = comb[2 * 512 + t * 64 + c];
            float4 o = acc[t];
            o.x += p0.x + p1.x + p2.x;
            o.y += p0.y + p1.y + p2.y;
            o.z += p0.z + p1.z + p2.z;
            o.w += p0.w + p1.w + p2.w;
            *reinterpret_cast<float4*>(&out[(size_t)(rowbase + t) * Hdim + c * 4]) = o;
        }
    }
}

// ---------------------------------------------------------------------------
extern "C" void kernel_launch(void* const* d_in, const int* in_sizes, int n_in,
                              void* d_out, int out_size)
{
    const float* h   = (const float*)d_in[0];
    const float* Wt  = (const float*)d_in[1];
    const float* Wtp = (const float*)d_in[2];
    const float* bh  = (const float*)d_in[3];
    const float* Wa  = (const float*)d_in[4];
    const float* ba  = (const float*)d_in[5];

    float* out  = (float*)d_out;                  // [B,S,H] = 524288
    float* attn = out + (size_t)NROWS * Hdim;     // [B,S,S] = 1048576

    proj_kernel<<<NROWS / KA_ROWS, 256>>>(h, Wt, Wtp, bh);
    score_kernel<<<Bdim * 32 * TSPLIT, 128>>>(Wa, ba, attn);
    out_kernel<<<NROWS / TT2, 256>>>(h, out, attn);
}